// round 4
// baseline (speedup 1.0000x reference)
#include <cuda_runtime.h>

#define N_USERS 100000
#define N_ITEMS 50000
#define N_NODES 150000
#define N_EDGES 4800000
#define EMBD    64
#define NLAYERS 3
#define BATCH   16384

#define RPW    4
#define FWARPS 8

#define SCAN_BLK   1024
#define SCAN_NBLK  ((N_NODES + SCAN_BLK - 1) / SCAN_BLK)   // 147
#define CNT_PAD    (SCAN_NBLK * SCAN_BLK)

typedef unsigned long long ull;

// Scratch (static __device__, no allocation)
__device__ float g_E[4][(size_t)N_NODES * EMBD];
__device__ float g_S[(size_t)N_NODES * EMBD];
__device__ int   g_cnt[CNT_PAD];
__device__ int   g_incl[CNT_PAD];
__device__ int   g_blockSums[SCAN_NBLK];
__device__ int   g_blockOff[SCAN_NBLK];
__device__ int   g_rowstart[N_NODES];
__device__ int   g_cursor[N_NODES];
__device__ int2  g_edge[N_EDGES];   // (col, val-as-int)

// ---------------- f32x2 helpers ----------------
__device__ __forceinline__ ull f2fma(ull a, ull b, ull c) {
    ull d; asm("fma.rn.f32x2 %0, %1, %2, %3;" : "=l"(d) : "l"(a), "l"(b), "l"(c)); return d;
}
__device__ __forceinline__ ull f2mul(ull a, ull b) {
    ull d; asm("mul.rn.f32x2 %0, %1, %2;" : "=l"(d) : "l"(a), "l"(b)); return d;
}
__device__ __forceinline__ ull f2add(ull a, ull b) {
    ull d; asm("add.rn.f32x2 %0, %1, %2;" : "=l"(d) : "l"(a), "l"(b)); return d;
}
__device__ __forceinline__ ull dup2(float x) {
    ull d; asm("mov.b64 %0, {%1, %1};" : "=l"(d) : "f"(x)); return d;
}
__device__ __forceinline__ float2 unpk(ull a) {
    float2 r; asm("mov.b64 {%0, %1}, %2;" : "=f"(r.x), "=f"(r.y) : "l"(a)); return r;
}

// ---------------------------------------------------------------------------
__global__ __launch_bounds__(256) void k_concat(const float4* __restrict__ ue,
                                                const float4* __restrict__ ie) {
    int i = blockIdx.x * 256 + threadIdx.x;
    const int nu4 = N_USERS * 16;
    const int nt4 = N_NODES * 16;
    if (i >= nt4) return;
    float4 v = (i < nu4) ? __ldg(&ue[i]) : __ldg(&ie[i - nu4]);
    reinterpret_cast<float4*>(g_E[0])[i] = v;
}

// ---------------- CSR build ----------------
__global__ __launch_bounds__(256) void k_reset() {
    int i = blockIdx.x * 256 + threadIdx.x;
    if (i < CNT_PAD) g_cnt[i] = 0;
}

__global__ __launch_bounds__(256) void k_hist(const int* __restrict__ rows, int nedges) {
    int e = blockIdx.x * 256 + threadIdx.x;
    if (e >= nedges) return;
    atomicAdd(&g_cnt[__ldcs(&rows[e])], 1);
}

__global__ __launch_bounds__(SCAN_BLK) void k_scan1() {
    __shared__ int temp[SCAN_BLK];
    int tid = threadIdx.x;
    int gi = blockIdx.x * SCAN_BLK + tid;
    int x = g_cnt[gi];
    temp[tid] = x;
    __syncthreads();
#pragma unroll
    for (int off = 1; off < SCAN_BLK; off <<= 1) {
        int t = (tid >= off) ? temp[tid - off] : 0;
        __syncthreads();
        temp[tid] += t;
        __syncthreads();
    }
    g_incl[gi] = temp[tid];
    if (tid == SCAN_BLK - 1) g_blockSums[blockIdx.x] = temp[tid];
}

__global__ void k_scan2() {
    if (threadIdx.x == 0) {
        int run = 0;
        for (int i = 0; i < SCAN_NBLK; i++) { g_blockOff[i] = run; run += g_blockSums[i]; }
    }
}

__global__ __launch_bounds__(256) void k_scan3() {
    int i = blockIdx.x * 256 + threadIdx.x;
    if (i >= N_NODES) return;
    int b = i / SCAN_BLK;
    int excl = g_incl[i] - g_cnt[i] + g_blockOff[b];
    g_rowstart[i] = excl;
    g_cursor[i] = excl;
}

__global__ __launch_bounds__(256) void k_scatter(const int* __restrict__ rows,
                                                 const int* __restrict__ cols,
                                                 const float* __restrict__ vals,
                                                 int nedges) {
    int e = blockIdx.x * 256 + threadIdx.x;
    if (e >= nedges) return;
    int r = __ldcs(&rows[e]);
    int pos = atomicAdd(&g_cursor[r], 1);
    g_edge[pos] = make_int2(__ldcs(&cols[e]), __float_as_int(__ldcs(&vals[e])));
}

// ---------------------------------------------------------------------------
// CSR SpMM: warp per row, lane owns 2 floats, packed f32x2 accum, dual chains.
// ---------------------------------------------------------------------------
__global__ __launch_bounds__(256) void k_spmm_csr(int in_idx) {
    int warp = (blockIdx.x * 256 + threadIdx.x) >> 5;
    int lane = threadIdx.x & 31;
    if (warp >= N_NODES) return;
    const float* __restrict__ E = g_E[in_idx];
    int j0 = lane * 2;
    int s = g_rowstart[warp];
    int end = s + g_cnt[warp];
    ull acc0 = 0ull, acc1 = 0ull;
    int e = s;
    for (; e + 4 <= end; e += 4) {
        int2 e0 = __ldg(&g_edge[e + 0]), e1 = __ldg(&g_edge[e + 1]);
        int2 e2 = __ldg(&g_edge[e + 2]), e3 = __ldg(&g_edge[e + 3]);
        ull x0 = *reinterpret_cast<const ull*>(E + (size_t)e0.x * 64 + j0);
        ull x1 = *reinterpret_cast<const ull*>(E + (size_t)e1.x * 64 + j0);
        ull x2 = *reinterpret_cast<const ull*>(E + (size_t)e2.x * 64 + j0);
        ull x3 = *reinterpret_cast<const ull*>(E + (size_t)e3.x * 64 + j0);
        acc0 = f2fma(dup2(__int_as_float(e0.y)), x0, acc0);
        acc1 = f2fma(dup2(__int_as_float(e1.y)), x1, acc1);
        acc0 = f2fma(dup2(__int_as_float(e2.y)), x2, acc0);
        acc1 = f2fma(dup2(__int_as_float(e3.y)), x3, acc1);
    }
    for (; e < end; e++) {
        int2 ed = __ldg(&g_edge[e]);
        ull x = *reinterpret_cast<const ull*>(E + (size_t)ed.x * 64 + j0);
        acc0 = f2fma(dup2(__int_as_float(ed.y)), x, acc0);
    }
    ull acc = f2add(acc0, acc1);
    *reinterpret_cast<ull*>(g_S + (size_t)warp * 64 + j0) = acc;
}

// ---------------------------------------------------------------------------
// Dense matvec with PRE-DUPLICATED weights in smem:
//   per k: 2x LDS.128 + 4 FFMA2  ->  FMA2-pipe bound.
// bufT: [64 k][RPW rows] floats. sWd: [64 k][64 j] of packed (w,w) ull.
// ---------------------------------------------------------------------------
__device__ __forceinline__ void matvecT(const float* __restrict__ bufT,
                                        const ull* __restrict__ sWd,
                                        int j0, ull bj0d, ull bj1d,
                                        ull& a0, ull& a1, ull& b0, ull& b1) {
    a0 = bj0d; a1 = bj0d;
    b0 = bj1d; b1 = bj1d;
#pragma unroll 8
    for (int k = 0; k < 64; k++) {
        ulonglong2 x = *reinterpret_cast<const ulonglong2*>(bufT + k * RPW);
        ulonglong2 w = *reinterpret_cast<const ulonglong2*>(sWd + k * 64 + j0);
        a0 = f2fma(x.x, w.x, a0);
        a1 = f2fma(x.y, w.x, a1);
        b0 = f2fma(x.x, w.y, b0);
        b1 = f2fma(x.y, w.y, b1);
    }
}

__global__ __launch_bounds__(256) void k_fused(int in_idx,
                                               const float* __restrict__ W1,
                                               const float* __restrict__ b1,
                                               const float* __restrict__ W2,
                                               const float* __restrict__ b2) {
    extern __shared__ char dsm[];
    ull*   sW1d = reinterpret_cast<ull*>(dsm);            // 4096 ull = 32KB
    ull*   sW2d = sW1d + 4096;                            // 32KB
    float* bufXs = reinterpret_cast<float*>(sW2d + 4096); // 8KB
    float* bufBs = bufXs + FWARPS * 64 * RPW;             // 8KB

    const float* E = g_E[in_idx];
    float* Eout = g_E[in_idx + 1];

    int tid = threadIdx.x;
    for (int i = tid; i < 4096; i += 256) {
        sW1d[i] = dup2(W1[i]);
        sW2d[i] = dup2(W2[i]);
    }
    __syncthreads();

    int w = tid >> 5, lane = tid & 31, j0 = lane * 2;
    int base = (blockIdx.x * FWARPS + w) * RPW;
    float* bx = bufXs + w * (64 * RPW);
    float* bb = bufBs + w * (64 * RPW);

    // load E rows + S rows, store transposed
#pragma unroll
    for (int r = 0; r < RPW; r++) {
        int row = base + r;
        float2 xv = make_float2(0.f, 0.f), sv = make_float2(0.f, 0.f);
        if (row < N_NODES) {
            xv = *reinterpret_cast<const float2*>(E + (size_t)row * 64 + j0);
            sv = *reinterpret_cast<const float2*>(g_S + (size_t)row * 64 + j0);
        }
        bx[(j0 + 0) * RPW + r] = xv.x;
        bx[(j0 + 1) * RPW + r] = xv.y;
        bb[(j0 + 0) * RPW + r] = sv.x;
        bb[(j0 + 1) * RPW + r] = sv.y;
    }
    __syncwarp();

    ull b1j0d = dup2(__ldg(&b1[j0])), b1j1d = dup2(__ldg(&b1[j0 + 1]));
    ull b2j0d = dup2(__ldg(&b2[j0])), b2j1d = dup2(__ldg(&b2[j0 + 1]));

    ull h00, h01, h10, h11, n00, n01, n10, n11, i00, i01, i10, i11;
    matvecT(bx, sW1d, j0, b1j0d, b1j1d, h00, h01, h10, h11);  // self
    matvecT(bb, sW2d, j0, b2j0d, b2j1d, n00, n01, n10, n11);  // neighbor
    __syncwarp();

    // interact input: t = neighbor * x, stored transposed
    *reinterpret_cast<ull*>(&bb[(j0 + 0) * RPW + 0]) =
        f2mul(n00, *reinterpret_cast<const ull*>(&bx[(j0 + 0) * RPW + 0]));
    *reinterpret_cast<ull*>(&bb[(j0 + 0) * RPW + 2]) =
        f2mul(n01, *reinterpret_cast<const ull*>(&bx[(j0 + 0) * RPW + 2]));
    *reinterpret_cast<ull*>(&bb[(j0 + 1) * RPW + 0]) =
        f2mul(n10, *reinterpret_cast<const ull*>(&bx[(j0 + 1) * RPW + 0]));
    *reinterpret_cast<ull*>(&bb[(j0 + 1) * RPW + 2]) =
        f2mul(n11, *reinterpret_cast<const ull*>(&bx[(j0 + 1) * RPW + 2]));
    __syncwarp();

    matvecT(bb, sW2d, j0, b2j0d, b2j1d, i00, i01, i10, i11);  // interact

    ull o00 = f2add(f2add(h00, n00), i00);
    ull o01 = f2add(f2add(h01, n01), i01);
    ull o10 = f2add(f2add(h10, n10), i10);
    ull o11 = f2add(f2add(h11, n11), i11);

    float2 p00 = unpk(o00), p01 = unpk(o01), p10 = unpk(o10), p11 = unpk(o11);
    float oc[RPW][2] = {{p00.x, p10.x}, {p00.y, p10.y}, {p01.x, p11.x}, {p01.y, p11.y}};
#pragma unroll
    for (int r = 0; r < RPW; r++) {
        int row = base + r;
        if (row < N_NODES) {
            float o0 = oc[r][0], o1 = oc[r][1];
            o0 = o0 > 0.f ? o0 : 0.2f * o0;
            o1 = o1 > 0.f ? o1 : 0.2f * o1;
            *reinterpret_cast<float2*>(Eout + (size_t)row * 64 + j0) = make_float2(o0, o1);
        }
    }
}

// ---------------------------------------------------------------------------
__global__ __launch_bounds__(256) void k_gather(const int* __restrict__ users,
                                                const int* __restrict__ pos,
                                                const int* __restrict__ neg,
                                                float4* __restrict__ out) {
    int gid = blockIdx.x * 256 + threadIdx.x;
    const int total = 3 * BATCH * 64;
    if (gid >= total) return;
    int c4 = gid & 63;
    int row = gid >> 6;
    int seg = row / BATCH;
    int b = row - seg * BATCH;
    int node;
    if (seg == 0)      node = __ldg(&users[b]);
    else if (seg == 1) node = N_USERS + __ldg(&pos[b]);
    else               node = N_USERS + __ldg(&neg[b]);
    int layer = c4 >> 4, w4 = c4 & 15;
    float4 v = __ldg(reinterpret_cast<const float4*>(g_E[layer]) + (size_t)node * 16 + w4);
    out[gid] = v;
}

// ---------------------------------------------------------------------------
extern "C" void kernel_launch(void* const* d_in, const int* in_sizes, int n_in,
                              void* d_out, int out_size) {
    const int*    users = (const int*)d_in[0];
    const int*    pos   = (const int*)d_in[1];
    const int*    neg   = (const int*)d_in[2];
    const int*    rows  = (const int*)d_in[3];
    const int*    cols  = (const int*)d_in[4];
    const float*  vals  = (const float*)d_in[5];
    const float4* ue    = (const float4*)d_in[6];
    const float4* ie    = (const float4*)d_in[7];
    const float*  W1s   = (const float*)d_in[8];
    const float*  b1s   = (const float*)d_in[9];
    const float*  W2s   = (const float*)d_in[10];
    const float*  b2s   = (const float*)d_in[11];
    int nedges = in_sizes[3];

    const int DSMEM = 81920;  // 64KB weights + 16KB buffers
    cudaFuncSetAttribute(k_fused, cudaFuncAttributeMaxDynamicSharedMemorySize, DSMEM);

    const int n4blocks = (N_NODES * 16 + 255) / 256;
    const int eblocks = (nedges + 255) / 256;

    k_concat<<<n4blocks, 256>>>(ue, ie);

    k_reset<<<(CNT_PAD + 255) / 256, 256>>>();
    k_hist<<<eblocks, 256>>>(rows, nedges);
    k_scan1<<<SCAN_NBLK, SCAN_BLK>>>();
    k_scan2<<<1, 32>>>();
    k_scan3<<<(N_NODES + 255) / 256, 256>>>();
    k_scatter<<<eblocks, 256>>>(rows, cols, vals, nedges);

    const int spmm_blocks = (N_NODES * 32 + 255) / 256;
    const int ngroups = (N_NODES + RPW * FWARPS - 1) / (RPW * FWARPS);
    for (int l = 0; l < NLAYERS; l++) {
        k_spmm_csr<<<spmm_blocks, 256>>>(l);
        k_fused<<<ngroups, 256, DSMEM>>>(l, W1s + l * 4096, b1s + l * 64,
                                         W2s + l * 4096, b2s + l * 64);
    }

    k_gather<<<(3 * BATCH * 64 + 255) / 256, 256>>>(users, pos, neg, (float4*)d_out);
}

// round 5
// speedup vs baseline: 1.4855x; 1.4855x over previous
#include <cuda_runtime.h>

#define N_USERS 100000
#define N_ITEMS 50000
#define N_NODES 150000
#define N_EDGES 4800000
#define EMBD    64
#define NLAYERS 3
#define BATCH   16384

#define SCAN_BLK   1024
#define SCAN_NBLK  ((N_NODES + SCAN_BLK - 1) / SCAN_BLK)   // 147
#define CNT_PAD    (SCAN_NBLK * SCAN_BLK)

#define TSTRIDE 68   // padded row stride (floats) for smem T tiles

typedef unsigned long long ull;

// Scratch (static __device__, no allocation)
__device__ float g_E[4][(size_t)N_NODES * EMBD];
__device__ float g_S[(size_t)N_NODES * EMBD];
__device__ int   g_cnt[CNT_PAD];
__device__ int   g_incl[CNT_PAD];
__device__ int   g_blockSums[SCAN_NBLK];
__device__ int   g_blockOff[SCAN_NBLK];
__device__ int   g_rowstart[N_NODES];
__device__ int   g_cursor[N_NODES];
__device__ int2  g_edge[N_EDGES];

// ---------------- f32x2 helpers (spmm) ----------------
__device__ __forceinline__ ull f2fma(ull a, ull b, ull c) {
    ull d; asm("fma.rn.f32x2 %0, %1, %2, %3;" : "=l"(d) : "l"(a), "l"(b), "l"(c)); return d;
}
__device__ __forceinline__ ull f2add(ull a, ull b) {
    ull d; asm("add.rn.f32x2 %0, %1, %2;" : "=l"(d) : "l"(a), "l"(b)); return d;
}
__device__ __forceinline__ ull dup2(float x) {
    ull d; asm("mov.b64 %0, {%1, %1};" : "=l"(d) : "f"(x)); return d;
}

// ---------------- tf32 split + mma helpers ----------------
__device__ __forceinline__ void tf32_split(float x, unsigned& hi, unsigned& lo) {
    unsigned h; asm("cvt.rna.tf32.f32 %0, %1;" : "=r"(h) : "f"(x));
    hi = h;
    lo = __float_as_uint(x - __uint_as_float(h));
}
__device__ __forceinline__ void mma_tf32(float* C,
                                         unsigned a0, unsigned a1, unsigned a2, unsigned a3,
                                         unsigned b0, unsigned b1) {
    asm volatile("mma.sync.aligned.m16n8k8.row.col.f32.tf32.tf32.f32 "
                 "{%0,%1,%2,%3},{%4,%5,%6,%7},{%8,%9},{%0,%1,%2,%3};"
                 : "+f"(C[0]), "+f"(C[1]), "+f"(C[2]), "+f"(C[3])
                 : "r"(a0), "r"(a1), "r"(a2), "r"(a3), "r"(b0), "r"(b1));
}

// ---------------------------------------------------------------------------
__global__ __launch_bounds__(256) void k_concat(const float4* __restrict__ ue,
                                                const float4* __restrict__ ie) {
    int i = blockIdx.x * 256 + threadIdx.x;
    const int nu4 = N_USERS * 16;
    const int nt4 = N_NODES * 16;
    if (i >= nt4) return;
    float4 v = (i < nu4) ? __ldg(&ue[i]) : __ldg(&ie[i - nu4]);
    reinterpret_cast<float4*>(g_E[0])[i] = v;
}

// ---------------- CSR build ----------------
__global__ __launch_bounds__(256) void k_reset() {
    int i = blockIdx.x * 256 + threadIdx.x;
    if (i < CNT_PAD) g_cnt[i] = 0;
}

__global__ __launch_bounds__(256) void k_hist(const int* __restrict__ rows, int nedges) {
    int e = blockIdx.x * 256 + threadIdx.x;
    if (e >= nedges) return;
    atomicAdd(&g_cnt[__ldcs(&rows[e])], 1);
}

__global__ __launch_bounds__(SCAN_BLK) void k_scan1() {
    __shared__ int temp[SCAN_BLK];
    int tid = threadIdx.x;
    int gi = blockIdx.x * SCAN_BLK + tid;
    int x = g_cnt[gi];
    temp[tid] = x;
    __syncthreads();
#pragma unroll
    for (int off = 1; off < SCAN_BLK; off <<= 1) {
        int t = (tid >= off) ? temp[tid - off] : 0;
        __syncthreads();
        temp[tid] += t;
        __syncthreads();
    }
    g_incl[gi] = temp[tid];
    if (tid == SCAN_BLK - 1) g_blockSums[blockIdx.x] = temp[tid];
}

__global__ void k_scan2() {
    if (threadIdx.x == 0) {
        int run = 0;
        for (int i = 0; i < SCAN_NBLK; i++) { g_blockOff[i] = run; run += g_blockSums[i]; }
    }
}

__global__ __launch_bounds__(256) void k_scan3() {
    int i = blockIdx.x * 256 + threadIdx.x;
    if (i >= N_NODES) return;
    int b = i / SCAN_BLK;
    int excl = g_incl[i] - g_cnt[i] + g_blockOff[b];
    g_rowstart[i] = excl;
    g_cursor[i] = excl;
}

__global__ __launch_bounds__(256) void k_scatter(const int* __restrict__ rows,
                                                 const int* __restrict__ cols,
                                                 const float* __restrict__ vals,
                                                 int nedges) {
    int e = blockIdx.x * 256 + threadIdx.x;
    if (e >= nedges) return;
    int r = __ldcs(&rows[e]);
    int pos = atomicAdd(&g_cursor[r], 1);
    g_edge[pos] = make_int2(__ldcs(&cols[e]), __float_as_int(__ldcs(&vals[e])));
}

// ---------------------------------------------------------------------------
// CSR SpMM: warp per row, lane owns 2 floats, packed f32x2 accum.
// ---------------------------------------------------------------------------
__global__ __launch_bounds__(256) void k_spmm_csr(int in_idx) {
    int warp = (blockIdx.x * 256 + threadIdx.x) >> 5;
    int lane = threadIdx.x & 31;
    if (warp >= N_NODES) return;
    const float* __restrict__ E = g_E[in_idx];
    int j0 = lane * 2;
    int s = g_rowstart[warp];
    int end = s + g_cnt[warp];
    ull acc0 = 0ull, acc1 = 0ull;
    int e = s;
    for (; e + 4 <= end; e += 4) {
        int2 e0 = __ldg(&g_edge[e + 0]), e1 = __ldg(&g_edge[e + 1]);
        int2 e2 = __ldg(&g_edge[e + 2]), e3 = __ldg(&g_edge[e + 3]);
        ull x0 = *reinterpret_cast<const ull*>(E + (size_t)e0.x * 64 + j0);
        ull x1 = *reinterpret_cast<const ull*>(E + (size_t)e1.x * 64 + j0);
        ull x2 = *reinterpret_cast<const ull*>(E + (size_t)e2.x * 64 + j0);
        ull x3 = *reinterpret_cast<const ull*>(E + (size_t)e3.x * 64 + j0);
        acc0 = f2fma(dup2(__int_as_float(e0.y)), x0, acc0);
        acc1 = f2fma(dup2(__int_as_float(e1.y)), x1, acc1);
        acc0 = f2fma(dup2(__int_as_float(e2.y)), x2, acc0);
        acc1 = f2fma(dup2(__int_as_float(e3.y)), x3, acc1);
    }
    for (; e < end; e++) {
        int2 ed = __ldg(&g_edge[e]);
        ull x = *reinterpret_cast<const ull*>(E + (size_t)ed.x * 64 + j0);
        acc0 = f2fma(dup2(__int_as_float(ed.y)), x, acc0);
    }
    *reinterpret_cast<ull*>(g_S + (size_t)warp * 64 + j0) = f2add(acc0, acc1);
}

// ---------------------------------------------------------------------------
// Tensor-core dense layer (tf32 split-3 -> ~fp32 precision).
// CTA = 256 thr = 8 warps; warp owns 32 rows x 64 cols.
// C accumulates: (S@W2) -> T=C*E -> += T@W2 -> += E@W1 -> +b1+b2 -> LReLU.
// Weights pre-split in smem as (hi,lo) float2. T in padded smem (stride 68).
// ---------------------------------------------------------------------------
__device__ __forceinline__ void pass_global(float C[2][8][4],
                                            const float* __restrict__ A,
                                            int rowbase,
                                            const float2* __restrict__ sWp,
                                            int grp, int tig) {
#pragma unroll
    for (int k0 = 0; k0 < 64; k0 += 8) {
        unsigned ah[2][4], al[2][4];
#pragma unroll
        for (int mt = 0; mt < 2; mt++) {
            int r0 = rowbase + mt * 16 + grp;
            int r1 = r0 + 8;
            r0 = min(r0, N_NODES - 1);
            r1 = min(r1, N_NODES - 1);
            int c = k0 + tig;
            float x0 = A[(size_t)r0 * 64 + c];
            float x1 = A[(size_t)r1 * 64 + c];
            float x2 = A[(size_t)r0 * 64 + c + 4];
            float x3 = A[(size_t)r1 * 64 + c + 4];
            tf32_split(x0, ah[mt][0], al[mt][0]);
            tf32_split(x1, ah[mt][1], al[mt][1]);
            tf32_split(x2, ah[mt][2], al[mt][2]);
            tf32_split(x3, ah[mt][3], al[mt][3]);
        }
#pragma unroll
        for (int nt = 0; nt < 8; nt++) {
            float2 w0 = sWp[(k0 + tig) * 64 + nt * 8 + grp];
            float2 w1 = sWp[(k0 + tig + 4) * 64 + nt * 8 + grp];
            unsigned bh0 = __float_as_uint(w0.x), bl0 = __float_as_uint(w0.y);
            unsigned bh1 = __float_as_uint(w1.x), bl1 = __float_as_uint(w1.y);
#pragma unroll
            for (int mt = 0; mt < 2; mt++) {
                mma_tf32(C[mt][nt], ah[mt][0], ah[mt][1], ah[mt][2], ah[mt][3], bh0, bh1);
                mma_tf32(C[mt][nt], ah[mt][0], ah[mt][1], ah[mt][2], ah[mt][3], bl0, bl1);
                mma_tf32(C[mt][nt], al[mt][0], al[mt][1], al[mt][2], al[mt][3], bh0, bh1);
            }
        }
    }
}

__device__ __forceinline__ void pass_smem(float C[2][8][4],
                                          const float* __restrict__ T,
                                          const float2* __restrict__ sWp,
                                          int grp, int tig) {
#pragma unroll
    for (int k0 = 0; k0 < 64; k0 += 8) {
        unsigned ah[2][4], al[2][4];
#pragma unroll
        for (int mt = 0; mt < 2; mt++) {
            int lr0 = mt * 16 + grp;
            int c = k0 + tig;
            float x0 = T[lr0 * TSTRIDE + c];
            float x1 = T[(lr0 + 8) * TSTRIDE + c];
            float x2 = T[lr0 * TSTRIDE + c + 4];
            float x3 = T[(lr0 + 8) * TSTRIDE + c + 4];
            tf32_split(x0, ah[mt][0], al[mt][0]);
            tf32_split(x1, ah[mt][1], al[mt][1]);
            tf32_split(x2, ah[mt][2], al[mt][2]);
            tf32_split(x3, ah[mt][3], al[mt][3]);
        }
#pragma unroll
        for (int nt = 0; nt < 8; nt++) {
            float2 w0 = sWp[(k0 + tig) * 64 + nt * 8 + grp];
            float2 w1 = sWp[(k0 + tig + 4) * 64 + nt * 8 + grp];
            unsigned bh0 = __float_as_uint(w0.x), bl0 = __float_as_uint(w0.y);
            unsigned bh1 = __float_as_uint(w1.x), bl1 = __float_as_uint(w1.y);
#pragma unroll
            for (int mt = 0; mt < 2; mt++) {
                mma_tf32(C[mt][nt], ah[mt][0], ah[mt][1], ah[mt][2], ah[mt][3], bh0, bh1);
                mma_tf32(C[mt][nt], ah[mt][0], ah[mt][1], ah[mt][2], ah[mt][3], bl0, bl1);
                mma_tf32(C[mt][nt], al[mt][0], al[mt][1], al[mt][2], al[mt][3], bh0, bh1);
            }
        }
    }
}

__global__ __launch_bounds__(256) void k_dense(int in_idx,
                                               const float* __restrict__ W1,
                                               const float* __restrict__ b1,
                                               const float* __restrict__ W2,
                                               const float* __restrict__ b2) {
    extern __shared__ float2 smem_dyn[];
    float2* sW1p = smem_dyn;             // 4096 float2 = 32KB
    float2* sW2p = smem_dyn + 4096;      // 32KB
    float*  sT   = reinterpret_cast<float*>(smem_dyn + 8192);  // 8*32*68 floats

    const float* E = g_E[in_idx];
    float* Eout = g_E[in_idx + 1];

    int tid = threadIdx.x;
    for (int i = tid; i < 4096; i += 256) {
        float w1 = W1[i], w2 = W2[i];
        unsigned h;
        asm("cvt.rna.tf32.f32 %0, %1;" : "=r"(h) : "f"(w1));
        float hf = __uint_as_float(h);
        sW1p[i] = make_float2(hf, w1 - hf);
        asm("cvt.rna.tf32.f32 %0, %1;" : "=r"(h) : "f"(w2));
        hf = __uint_as_float(h);
        sW2p[i] = make_float2(hf, w2 - hf);
    }
    __syncthreads();

    int w = tid >> 5, lane = tid & 31;
    int grp = lane >> 2, tig = lane & 3;
    int rowbase = blockIdx.x * 256 + w * 32;
    float* myT = sT + w * (32 * TSTRIDE);

    float C[2][8][4];
#pragma unroll
    for (int nt = 0; nt < 8; nt++) {
        int col = nt * 8 + tig * 2;
        float v0 = __ldg(&b2[col]), v1 = __ldg(&b2[col + 1]);
        C[0][nt][0] = v0; C[0][nt][1] = v1; C[0][nt][2] = v0; C[0][nt][3] = v1;
        C[1][nt][0] = v0; C[1][nt][1] = v1; C[1][nt][2] = v0; C[1][nt][3] = v1;
    }

    // Pass 1: C = S @ W2 + b2  (= neighbor)
    pass_global(C, g_S, rowbase, sW2p, grp, tig);

    // T = neighbor * E  (elementwise), to padded smem
#pragma unroll
    for (int mt = 0; mt < 2; mt++) {
        int lr0 = mt * 16 + grp;
        int gr0 = rowbase + lr0;
        int cr0 = min(gr0, N_NODES - 1);
        int cr1 = min(gr0 + 8, N_NODES - 1);
#pragma unroll
        for (int nt = 0; nt < 8; nt++) {
            int col = nt * 8 + tig * 2;
            float2 e0 = *reinterpret_cast<const float2*>(E + (size_t)cr0 * 64 + col);
            float2 e1 = *reinterpret_cast<const float2*>(E + (size_t)cr1 * 64 + col);
            *reinterpret_cast<float2*>(myT + lr0 * TSTRIDE + col) =
                make_float2(C[mt][nt][0] * e0.x, C[mt][nt][1] * e0.y);
            *reinterpret_cast<float2*>(myT + (lr0 + 8) * TSTRIDE + col) =
                make_float2(C[mt][nt][2] * e1.x, C[mt][nt][3] * e1.y);
        }
    }
    __syncwarp();

    // Pass 2: C += T @ W2
    pass_smem(C, myT, sW2p, grp, tig);

    // Pass 3: C += E @ W1
    pass_global(C, E, rowbase, sW1p, grp, tig);

    // out = LReLU(C + b1 + b2)
#pragma unroll
    for (int mt = 0; mt < 2; mt++) {
        int r0 = rowbase + mt * 16 + grp;
        int r1 = r0 + 8;
#pragma unroll
        for (int nt = 0; nt < 8; nt++) {
            int col = nt * 8 + tig * 2;
            float bb0 = __ldg(&b1[col]) + __ldg(&b2[col]);
            float bb1 = __ldg(&b1[col + 1]) + __ldg(&b2[col + 1]);
            if (r0 < N_NODES) {
                float o0 = C[mt][nt][0] + bb0;
                float o1 = C[mt][nt][1] + bb1;
                o0 = o0 > 0.f ? o0 : 0.2f * o0;
                o1 = o1 > 0.f ? o1 : 0.2f * o1;
                *reinterpret_cast<float2*>(Eout + (size_t)r0 * 64 + col) = make_float2(o0, o1);
            }
            if (r1 < N_NODES) {
                float o2 = C[mt][nt][2] + bb0;
                float o3 = C[mt][nt][3] + bb1;
                o2 = o2 > 0.f ? o2 : 0.2f * o2;
                o3 = o3 > 0.f ? o3 : 0.2f * o3;
                *reinterpret_cast<float2*>(Eout + (size_t)r1 * 64 + col) = make_float2(o2, o3);
            }
        }
    }
}

// ---------------------------------------------------------------------------
__global__ __launch_bounds__(256) void k_gather(const int* __restrict__ users,
                                                const int* __restrict__ pos,
                                                const int* __restrict__ neg,
                                                float4* __restrict__ out) {
    int gid = blockIdx.x * 256 + threadIdx.x;
    const int total = 3 * BATCH * 64;
    if (gid >= total) return;
    int c4 = gid & 63;
    int row = gid >> 6;
    int seg = row / BATCH;
    int b = row - seg * BATCH;
    int node;
    if (seg == 0)      node = __ldg(&users[b]);
    else if (seg == 1) node = N_USERS + __ldg(&pos[b]);
    else               node = N_USERS + __ldg(&neg[b]);
    int layer = c4 >> 4, w4 = c4 & 15;
    float4 v = __ldg(reinterpret_cast<const float4*>(g_E[layer]) + (size_t)node * 16 + w4);
    out[gid] = v;
}

// ---------------------------------------------------------------------------
extern "C" void kernel_launch(void* const* d_in, const int* in_sizes, int n_in,
                              void* d_out, int out_size) {
    const int*    users = (const int*)d_in[0];
    const int*    pos   = (const int*)d_in[1];
    const int*    neg   = (const int*)d_in[2];
    const int*    rows  = (const int*)d_in[3];
    const int*    cols  = (const int*)d_in[4];
    const float*  vals  = (const float*)d_in[5];
    const float4* ue    = (const float4*)d_in[6];
    const float4* ie    = (const float4*)d_in[7];
    const float*  W1s   = (const float*)d_in[8];
    const float*  b1s   = (const float*)d_in[9];
    const float*  W2s   = (const float*)d_in[10];
    const float*  b2s   = (const float*)d_in[11];
    int nedges = in_sizes[3];

    // 64KB split weights + 8 * 32*68*4B T tiles = 65536 + 69632 = 135168 B
    const int DSMEM = 65536 + 8 * 32 * TSTRIDE * 4;
    static int configured = 0;
    if (!configured) {
        cudaFuncSetAttribute(k_dense, cudaFuncAttributeMaxDynamicSharedMemorySize, DSMEM);
        configured = 1;
    }

    const int n4blocks = (N_NODES * 16 + 255) / 256;
    const int eblocks = (nedges + 255) / 256;

    k_concat<<<n4blocks, 256>>>(ue, ie);

    k_reset<<<(CNT_PAD + 255) / 256, 256>>>();
    k_hist<<<eblocks, 256>>>(rows, nedges);
    k_scan1<<<SCAN_NBLK, SCAN_BLK>>>();
    k_scan2<<<1, 32>>>();
    k_scan3<<<(N_NODES + 255) / 256, 256>>>();
    k_scatter<<<eblocks, 256>>>(rows, cols, vals, nedges);

    const int spmm_blocks = (N_NODES * 32 + 255) / 256;
    const int dense_blocks = (N_NODES + 255) / 256;
    for (int l = 0; l < NLAYERS; l++) {
        k_spmm_csr<<<spmm_blocks, 256>>>(l);
        k_dense<<<dense_blocks, 256, DSMEM>>>(l, W1s + l * 4096, b1s + l * 64,
                                              W2s + l * 4096, b2s + l * 64);
    }

    k_gather<<<(3 * BATCH * 64 + 255) / 256, 256>>>(users, pos, neg, (float4*)d_out);
}

// round 6
// speedup vs baseline: 1.6183x; 1.0894x over previous
#include <cuda_runtime.h>

#define N_USERS 100000
#define N_ITEMS 50000
#define N_NODES 150000
#define N_EDGES 4800000
#define EMBD    64
#define NLAYERS 3
#define BATCH   16384

#define SCAN_BLK   1024
#define SCAN_NBLK  ((N_NODES + SCAN_BLK - 1) / SCAN_BLK)   // 147
#define CNT_PAD    (SCAN_NBLK * SCAN_BLK)

#define TSTRIDE 68   // padded row stride (floats) for smem T tiles
#define WSTRIDE 72   // padded row stride (float2) for smem split weights

typedef unsigned long long ull;

// Scratch (static __device__, no allocation)
__device__ float g_E[4][(size_t)N_NODES * EMBD];
__device__ float g_S[(size_t)N_NODES * EMBD];
__device__ int   g_cnt[CNT_PAD];
__device__ int   g_incl[CNT_PAD];
__device__ int   g_blockSums[SCAN_NBLK];
__device__ int   g_blockOff[SCAN_NBLK];
__device__ int   g_rowstart[N_NODES];
__device__ int   g_cursor[N_NODES];
__device__ int2  g_edge[N_EDGES];

// ---------------- f32x2 helpers (spmm) ----------------
__device__ __forceinline__ ull f2fma(ull a, ull b, ull c) {
    ull d; asm("fma.rn.f32x2 %0, %1, %2, %3;" : "=l"(d) : "l"(a), "l"(b), "l"(c)); return d;
}
__device__ __forceinline__ ull f2add(ull a, ull b) {
    ull d; asm("add.rn.f32x2 %0, %1, %2;" : "=l"(d) : "l"(a), "l"(b)); return d;
}
__device__ __forceinline__ ull dup2(float x) {
    ull d; asm("mov.b64 %0, {%1, %1};" : "=l"(d) : "f"(x)); return d;
}

// ---------------- tf32 split + mma helpers ----------------
__device__ __forceinline__ void tf32_split(float x, unsigned& hi, unsigned& lo) {
    unsigned h; asm("cvt.rna.tf32.f32 %0, %1;" : "=r"(h) : "f"(x));
    hi = h;
    lo = __float_as_uint(x - __uint_as_float(h));
}
__device__ __forceinline__ void mma_tf32(float* C,
                                         unsigned a0, unsigned a1, unsigned a2, unsigned a3,
                                         unsigned b0, unsigned b1) {
    asm volatile("mma.sync.aligned.m16n8k8.row.col.f32.tf32.tf32.f32 "
                 "{%0,%1,%2,%3},{%4,%5,%6,%7},{%8,%9},{%0,%1,%2,%3};"
                 : "+f"(C[0]), "+f"(C[1]), "+f"(C[2]), "+f"(C[3])
                 : "r"(a0), "r"(a1), "r"(a2), "r"(a3), "r"(b0), "r"(b1));
}

// ---------------------------------------------------------------------------
// E0 = concat(user_emb, item_emb); also zeroes the CSR histogram counters.
// ---------------------------------------------------------------------------
__global__ __launch_bounds__(256) void k_concat(const float4* __restrict__ ue,
                                                const float4* __restrict__ ie) {
    int i = blockIdx.x * 256 + threadIdx.x;
    const int nu4 = N_USERS * 16;
    const int nt4 = N_NODES * 16;
    if (i < CNT_PAD) g_cnt[i] = 0;
    if (i >= nt4) return;
    float4 v = (i < nu4) ? __ldg(&ue[i]) : __ldg(&ie[i - nu4]);
    reinterpret_cast<float4*>(g_E[0])[i] = v;
}

// ---------------- CSR build ----------------
__global__ __launch_bounds__(256) void k_hist(const int* __restrict__ rows, int nedges) {
    int e = blockIdx.x * 256 + threadIdx.x;
    if (e >= nedges) return;
    atomicAdd(&g_cnt[__ldcs(&rows[e])], 1);
}

__global__ __launch_bounds__(SCAN_BLK) void k_scan1() {
    __shared__ int temp[SCAN_BLK];
    int tid = threadIdx.x;
    int gi = blockIdx.x * SCAN_BLK + tid;
    int x = g_cnt[gi];
    temp[tid] = x;
    __syncthreads();
#pragma unroll
    for (int off = 1; off < SCAN_BLK; off <<= 1) {
        int t = (tid >= off) ? temp[tid - off] : 0;
        __syncthreads();
        temp[tid] += t;
        __syncthreads();
    }
    g_incl[gi] = temp[tid];
    if (tid == SCAN_BLK - 1) g_blockSums[blockIdx.x] = temp[tid];
}

__global__ void k_scan2() {
    if (threadIdx.x == 0) {
        int run = 0;
        for (int i = 0; i < SCAN_NBLK; i++) { g_blockOff[i] = run; run += g_blockSums[i]; }
    }
}

__global__ __launch_bounds__(256) void k_scan3() {
    int i = blockIdx.x * 256 + threadIdx.x;
    if (i >= N_NODES) return;
    int b = i / SCAN_BLK;
    int excl = g_incl[i] - g_cnt[i] + g_blockOff[b];
    g_rowstart[i] = excl;
    g_cursor[i] = excl;
}

__global__ __launch_bounds__(256) void k_scatter(const int* __restrict__ rows,
                                                 const int* __restrict__ cols,
                                                 const float* __restrict__ vals,
                                                 int nedges) {
    int e = blockIdx.x * 256 + threadIdx.x;
    if (e >= nedges) return;
    int r = __ldcs(&rows[e]);
    int pos = atomicAdd(&g_cursor[r], 1);
    g_edge[pos] = make_int2(__ldcs(&cols[e]), __float_as_int(__ldcs(&vals[e])));
}

// ---------------------------------------------------------------------------
// CSR SpMM: 16 threads per row, lane owns one float4 chunk (LDG.128 gathers).
// ---------------------------------------------------------------------------
__global__ __launch_bounds__(256) void k_spmm_csr(int in_idx) {
    int t = blockIdx.x * 256 + threadIdx.x;
    int row = t >> 4;
    int c = t & 15;
    if (row >= N_NODES) return;
    const float4* __restrict__ E4 = reinterpret_cast<const float4*>(g_E[in_idx]);
    int s = g_rowstart[row];
    int end = s + g_cnt[row];
    ull a0x = 0, a0y = 0, a1x = 0, a1y = 0;
    int e = s;
    for (; e + 4 <= end; e += 4) {
        int2 e0 = __ldg(&g_edge[e + 0]), e1 = __ldg(&g_edge[e + 1]);
        int2 e2 = __ldg(&g_edge[e + 2]), e3 = __ldg(&g_edge[e + 3]);
        float4 x0 = __ldg(&E4[(size_t)e0.x * 16 + c]);
        float4 x1 = __ldg(&E4[(size_t)e1.x * 16 + c]);
        float4 x2 = __ldg(&E4[(size_t)e2.x * 16 + c]);
        float4 x3 = __ldg(&E4[(size_t)e3.x * 16 + c]);
        ull v0 = dup2(__int_as_float(e0.y)), v1 = dup2(__int_as_float(e1.y));
        ull v2 = dup2(__int_as_float(e2.y)), v3 = dup2(__int_as_float(e3.y));
        ulonglong2 p0 = *reinterpret_cast<ulonglong2*>(&x0);
        ulonglong2 p1 = *reinterpret_cast<ulonglong2*>(&x1);
        ulonglong2 p2 = *reinterpret_cast<ulonglong2*>(&x2);
        ulonglong2 p3 = *reinterpret_cast<ulonglong2*>(&x3);
        a0x = f2fma(v0, p0.x, a0x); a0y = f2fma(v0, p0.y, a0y);
        a1x = f2fma(v1, p1.x, a1x); a1y = f2fma(v1, p1.y, a1y);
        a0x = f2fma(v2, p2.x, a0x); a0y = f2fma(v2, p2.y, a0y);
        a1x = f2fma(v3, p3.x, a1x); a1y = f2fma(v3, p3.y, a1y);
    }
    for (; e < end; e++) {
        int2 ed = __ldg(&g_edge[e]);
        float4 x = __ldg(&E4[(size_t)ed.x * 16 + c]);
        ull v = dup2(__int_as_float(ed.y));
        ulonglong2 p = *reinterpret_cast<ulonglong2*>(&x);
        a0x = f2fma(v, p.x, a0x);
        a0y = f2fma(v, p.y, a0y);
    }
    ulonglong2 r;
    r.x = f2add(a0x, a1x);
    r.y = f2add(a0y, a1y);
    reinterpret_cast<ulonglong2*>(g_S)[(size_t)row * 16 + c] = r;
}

// ---------------------------------------------------------------------------
// Tensor-core dense layer, 512 threads, warp owns 16 rows x 64 cols.
// ---------------------------------------------------------------------------
__device__ __forceinline__ void pass_global(float C[8][4],
                                            const float* __restrict__ A,
                                            int rowbase,
                                            const float2* __restrict__ sWp,
                                            int grp, int tig) {
#pragma unroll
    for (int k0 = 0; k0 < 64; k0 += 8) {
        int r0 = min(rowbase + grp, N_NODES - 1);
        int r1 = min(rowbase + grp + 8, N_NODES - 1);
        int c = k0 + tig;
        unsigned ah[4], al[4];
        tf32_split(A[(size_t)r0 * 64 + c],     ah[0], al[0]);
        tf32_split(A[(size_t)r1 * 64 + c],     ah[1], al[1]);
        tf32_split(A[(size_t)r0 * 64 + c + 4], ah[2], al[2]);
        tf32_split(A[(size_t)r1 * 64 + c + 4], ah[3], al[3]);
#pragma unroll
        for (int nt = 0; nt < 8; nt++) {
            float2 w0 = sWp[(k0 + tig) * WSTRIDE + nt * 8 + grp];
            float2 w1 = sWp[(k0 + tig + 4) * WSTRIDE + nt * 8 + grp];
            unsigned bh0 = __float_as_uint(w0.x), bl0 = __float_as_uint(w0.y);
            unsigned bh1 = __float_as_uint(w1.x), bl1 = __float_as_uint(w1.y);
            mma_tf32(C[nt], ah[0], ah[1], ah[2], ah[3], bh0, bh1);
            mma_tf32(C[nt], ah[0], ah[1], ah[2], ah[3], bl0, bl1);
            mma_tf32(C[nt], al[0], al[1], al[2], al[3], bh0, bh1);
        }
    }
}

__device__ __forceinline__ void pass_smem(float C[8][4],
                                          const float* __restrict__ T,
                                          const float2* __restrict__ sWp,
                                          int grp, int tig) {
#pragma unroll
    for (int k0 = 0; k0 < 64; k0 += 8) {
        int c = k0 + tig;
        unsigned ah[4], al[4];
        tf32_split(T[grp * TSTRIDE + c],           ah[0], al[0]);
        tf32_split(T[(grp + 8) * TSTRIDE + c],     ah[1], al[1]);
        tf32_split(T[grp * TSTRIDE + c + 4],       ah[2], al[2]);
        tf32_split(T[(grp + 8) * TSTRIDE + c + 4], ah[3], al[3]);
#pragma unroll
        for (int nt = 0; nt < 8; nt++) {
            float2 w0 = sWp[(k0 + tig) * WSTRIDE + nt * 8 + grp];
            float2 w1 = sWp[(k0 + tig + 4) * WSTRIDE + nt * 8 + grp];
            unsigned bh0 = __float_as_uint(w0.x), bl0 = __float_as_uint(w0.y);
            unsigned bh1 = __float_as_uint(w1.x), bl1 = __float_as_uint(w1.y);
            mma_tf32(C[nt], ah[0], ah[1], ah[2], ah[3], bh0, bh1);
            mma_tf32(C[nt], ah[0], ah[1], ah[2], ah[3], bl0, bl1);
            mma_tf32(C[nt], al[0], al[1], al[2], al[3], bh0, bh1);
        }
    }
}

__global__ __launch_bounds__(512) void k_dense(int in_idx,
                                               const float* __restrict__ W1,
                                               const float* __restrict__ b1,
                                               const float* __restrict__ W2,
                                               const float* __restrict__ b2) {
    extern __shared__ float2 smem_dyn[];
    float2* sW1p = smem_dyn;                       // 64*WSTRIDE f2 = 36.9KB
    float2* sW2p = smem_dyn + 64 * WSTRIDE;        // 36.9KB
    float*  sT   = reinterpret_cast<float*>(smem_dyn + 2 * 64 * WSTRIDE);  // 16*16*68 f

    const float* E = g_E[in_idx];
    float* Eout = g_E[in_idx + 1];

    int tid = threadIdx.x;
    for (int i = tid; i < 4096; i += 512) {
        int k = i >> 6, col = i & 63;
        float w1 = W1[i], w2 = W2[i];
        unsigned h;
        asm("cvt.rna.tf32.f32 %0, %1;" : "=r"(h) : "f"(w1));
        float hf = __uint_as_float(h);
        sW1p[k * WSTRIDE + col] = make_float2(hf, w1 - hf);
        asm("cvt.rna.tf32.f32 %0, %1;" : "=r"(h) : "f"(w2));
        hf = __uint_as_float(h);
        sW2p[k * WSTRIDE + col] = make_float2(hf, w2 - hf);
    }
    __syncthreads();

    int w = tid >> 5, lane = tid & 31;
    int grp = lane >> 2, tig = lane & 3;
    int rowbase = blockIdx.x * 256 + w * 16;
    float* myT = sT + w * (16 * TSTRIDE);

    float C[8][4];
#pragma unroll
    for (int nt = 0; nt < 8; nt++) {
        int col = nt * 8 + tig * 2;
        float v0 = __ldg(&b2[col]), v1 = __ldg(&b2[col + 1]);
        C[nt][0] = v0; C[nt][1] = v1; C[nt][2] = v0; C[nt][3] = v1;
    }

    // Pass 1: C = S @ W2 + b2  (= neighbor)
    pass_global(C, g_S, rowbase, sW2p, grp, tig);

    // T = neighbor * E (elementwise) -> padded smem
    {
        int cr0 = min(rowbase + grp, N_NODES - 1);
        int cr1 = min(rowbase + grp + 8, N_NODES - 1);
#pragma unroll
        for (int nt = 0; nt < 8; nt++) {
            int col = nt * 8 + tig * 2;
            float2 e0 = *reinterpret_cast<const float2*>(E + (size_t)cr0 * 64 + col);
            float2 e1 = *reinterpret_cast<const float2*>(E + (size_t)cr1 * 64 + col);
            *reinterpret_cast<float2*>(myT + grp * TSTRIDE + col) =
                make_float2(C[nt][0] * e0.x, C[nt][1] * e0.y);
            *reinterpret_cast<float2*>(myT + (grp + 8) * TSTRIDE + col) =
                make_float2(C[nt][2] * e1.x, C[nt][3] * e1.y);
        }
    }
    __syncwarp();

    // Pass 2: C += T @ W2
    pass_smem(C, myT, sW2p, grp, tig);

    // Pass 3: C += E @ W1
    pass_global(C, E, rowbase, sW1p, grp, tig);

    // out = LReLU(C + b1 + b2-already-in)
    {
        int r0 = rowbase + grp;
        int r1 = rowbase + grp + 8;
#pragma unroll
        for (int nt = 0; nt < 8; nt++) {
            int col = nt * 8 + tig * 2;
            float bb0 = __ldg(&b1[col]) + __ldg(&b2[col]);
            float bb1 = __ldg(&b1[col + 1]) + __ldg(&b2[col + 1]);
            if (r0 < N_NODES) {
                float o0 = C[nt][0] + bb0;
                float o1 = C[nt][1] + bb1;
                o0 = o0 > 0.f ? o0 : 0.2f * o0;
                o1 = o1 > 0.f ? o1 : 0.2f * o1;
                *reinterpret_cast<float2*>(Eout + (size_t)r0 * 64 + col) = make_float2(o0, o1);
            }
            if (r1 < N_NODES) {
                float o2 = C[nt][2] + bb0;
                float o3 = C[nt][3] + bb1;
                o2 = o2 > 0.f ? o2 : 0.2f * o2;
                o3 = o3 > 0.f ? o3 : 0.2f * o3;
                *reinterpret_cast<float2*>(Eout + (size_t)r1 * 64 + col) = make_float2(o2, o3);
            }
        }
    }
}

// ---------------------------------------------------------------------------
__global__ __launch_bounds__(256) void k_gather(const int* __restrict__ users,
                                                const int* __restrict__ pos,
                                                const int* __restrict__ neg,
                                                float4* __restrict__ out) {
    int gid = blockIdx.x * 256 + threadIdx.x;
    const int total = 3 * BATCH * 64;
    if (gid >= total) return;
    int c4 = gid & 63;
    int row = gid >> 6;
    int seg = row / BATCH;
    int b = row - seg * BATCH;
    int node;
    if (seg == 0)      node = __ldg(&users[b]);
    else if (seg == 1) node = N_USERS + __ldg(&pos[b]);
    else               node = N_USERS + __ldg(&neg[b]);
    int layer = c4 >> 4, w4 = c4 & 15;
    float4 v = __ldg(reinterpret_cast<const float4*>(g_E[layer]) + (size_t)node * 16 + w4);
    out[gid] = v;
}

// ---------------------------------------------------------------------------
extern "C" void kernel_launch(void* const* d_in, const int* in_sizes, int n_in,
                              void* d_out, int out_size) {
    const int*    users = (const int*)d_in[0];
    const int*    pos   = (const int*)d_in[1];
    const int*    neg   = (const int*)d_in[2];
    const int*    rows  = (const int*)d_in[3];
    const int*    cols  = (const int*)d_in[4];
    const float*  vals  = (const float*)d_in[5];
    const float4* ue    = (const float4*)d_in[6];
    const float4* ie    = (const float4*)d_in[7];
    const float*  W1s   = (const float*)d_in[8];
    const float*  b1s   = (const float*)d_in[9];
    const float*  W2s   = (const float*)d_in[10];
    const float*  b2s   = (const float*)d_in[11];
    int nedges = in_sizes[3];

    // 2 * 64*72*8 B weights + 16 * 16*68*4 B T tiles = 73728 + 69632 = 143360 B
    const int DSMEM = 2 * 64 * WSTRIDE * 8 + 16 * 16 * TSTRIDE * 4;
    static int configured = 0;
    if (!configured) {
        cudaFuncSetAttribute(k_dense, cudaFuncAttributeMaxDynamicSharedMemorySize, DSMEM);
        configured = 1;
    }

    const int n4blocks = (N_NODES * 16 + 255) / 256;
    const int eblocks = (nedges + 255) / 256;

    k_concat<<<n4blocks, 256>>>(ue, ie);

    k_hist<<<eblocks, 256>>>(rows, nedges);
    k_scan1<<<SCAN_NBLK, SCAN_BLK>>>();
    k_scan2<<<1, 32>>>();
    k_scan3<<<(N_NODES + 255) / 256, 256>>>();
    k_scatter<<<eblocks, 256>>>(rows, cols, vals, nedges);

    const int spmm_blocks = (N_NODES * 16 + 255) / 256;
    const int dense_blocks = (N_NODES + 255) / 256;
    for (int l = 0; l < NLAYERS; l++) {
        k_spmm_csr<<<spmm_blocks, 256>>>(l);
        k_dense<<<dense_blocks, 512, DSMEM>>>(l, W1s + l * 4096, b1s + l * 64,
                                              W2s + l * 4096, b2s + l * 64);
    }

    k_gather<<<(3 * BATCH * 64 + 255) / 256, 256>>>(users, pos, neg, (float4*)d_out);
}